// round 1
// baseline (speedup 1.0000x reference)
#include <cuda_runtime.h>

#define IN 784
#define HIDN 64
#define KTOP 20

// Transposed weight scratch (allowed: __device__ globals, no allocation)
__device__ float g_WtE[IN * HIDN];   // [k][j]  = W_enc[j][k]
__device__ float g_WtD[HIDN * IN];   // [j][i]  = W_dec[i][j]

// ---- f32x2 packed-FMA helpers (sm_100+; ptxas won't auto-fuse, must be PTX) ----
__device__ __forceinline__ unsigned long long pk_dup(float v) {
    unsigned long long r; unsigned u = __float_as_uint(v);
    asm("mov.b64 %0, {%1, %2};" : "=l"(r) : "r"(u), "r"(u));
    return r;
}
__device__ __forceinline__ void upk(unsigned long long v, float &lo, float &hi) {
    unsigned a, b;
    asm("mov.b64 {%0, %1}, %2;" : "=r"(a), "=r"(b) : "l"(v));
    lo = __uint_as_float(a); hi = __uint_as_float(b);
}
__device__ __forceinline__ void fma2(unsigned long long &acc, unsigned long long a, unsigned long long b) {
    asm("fma.rn.f32x2 %0, %1, %2, %0;" : "+l"(acc) : "l"(a), "l"(b));
}

// ---------------- K0: transpose both weight matrices ----------------
__global__ void k_prep(const float* __restrict__ We, const float* __restrict__ Wd) {
    int idx = blockIdx.x * 256 + threadIdx.x;
    if (idx < IN * HIDN) {
        int j = idx & (HIDN - 1), k = idx >> 6;     // idx = k*64 + j
        g_WtE[idx] = We[j * IN + k];
        int i = idx % IN, jj = idx / IN;            // idx = jj*784 + i
        g_WtD[idx] = Wd[i * HIDN + jj];
    }
}

// ---------------- K1: encoder GEMM + bias + ReLU ----------------
// CTA: 128 rows x 64 cols, K=784 in chunks of 16. Thread tile 8 rows x 4 cols.
// Accumulators packed as row-pairs in f32x2 (low = even row).
__global__ __launch_bounds__(256) void k_enc(const float* __restrict__ x,
        const float* __restrict__ benc, float* __restrict__ hout, int B) {
    __shared__ float xs[16][132];   // transposed x chunk: xs[k][row], padded
    __shared__ float ws[16][64];    // WtE chunk: ws[k][j]
    const int tid = threadIdx.x;
    const int tx = tid & 15, ty = tid >> 4;
    const int r0 = blockIdx.x * 128;
    const int c0 = tx * 4;

    unsigned long long acc[4][4];
    #pragma unroll
    for (int i = 0; i < 4; i++)
        #pragma unroll
        for (int j = 0; j < 4; j++) acc[i][j] = 0ull;

    for (int kb = 0; kb < IN; kb += 16) {
        #pragma unroll
        for (int i = 0; i < 2; i++) {
            int idx = tid + i * 256;
            int row = idx >> 2, kq = idx & 3;
            int gr = r0 + row; if (gr >= B) gr = B - 1;
            float4 v = *(const float4*)(x + (size_t)gr * IN + kb + kq * 4);
            xs[kq*4+0][row] = v.x; xs[kq*4+1][row] = v.y;
            xs[kq*4+2][row] = v.z; xs[kq*4+3][row] = v.w;
        }
        {
            int k = tid >> 4, j4 = tid & 15;
            *(float4*)&ws[k][j4*4] = *(const float4*)(g_WtE + (kb + k) * HIDN + j4 * 4);
        }
        __syncthreads();
        #pragma unroll
        for (int k = 0; k < 16; k++) {
            const ulonglong2* ap = (const ulonglong2*)&xs[k][ty * 8];
            ulonglong2 a01 = ap[0];   // rows (0,1),(2,3) of the 8-row tile
            ulonglong2 a23 = ap[1];   // rows (4,5),(6,7)
            float4 b = *(const float4*)&ws[k][c0];
            unsigned long long b0 = pk_dup(b.x), b1 = pk_dup(b.y),
                               b2 = pk_dup(b.z), b3 = pk_dup(b.w);
            fma2(acc[0][0], a01.x, b0); fma2(acc[0][1], a01.x, b1);
            fma2(acc[0][2], a01.x, b2); fma2(acc[0][3], a01.x, b3);
            fma2(acc[1][0], a01.y, b0); fma2(acc[1][1], a01.y, b1);
            fma2(acc[1][2], a01.y, b2); fma2(acc[1][3], a01.y, b3);
            fma2(acc[2][0], a23.x, b0); fma2(acc[2][1], a23.x, b1);
            fma2(acc[2][2], a23.x, b2); fma2(acc[2][3], a23.x, b3);
            fma2(acc[3][0], a23.y, b0); fma2(acc[3][1], a23.y, b1);
            fma2(acc[3][2], a23.y, b2); fma2(acc[3][3], a23.y, b3);
        }
        __syncthreads();
    }

    float be0 = benc[c0+0], be1 = benc[c0+1], be2 = benc[c0+2], be3 = benc[c0+3];
    #pragma unroll
    for (int rp = 0; rp < 4; rp++) {
        float l0,h0,l1,h1,l2,h2,l3,h3;
        upk(acc[rp][0], l0, h0); upk(acc[rp][1], l1, h1);
        upk(acc[rp][2], l2, h2); upk(acc[rp][3], l3, h3);
        int r = r0 + ty * 8 + rp * 2;
        if (r < B) {
            float4 o = make_float4(fmaxf(l0+be0,0.f), fmaxf(l1+be1,0.f),
                                   fmaxf(l2+be2,0.f), fmaxf(l3+be3,0.f));
            *(float4*)(hout + (size_t)r * HIDN + c0) = o;
        }
        if (r + 1 < B) {
            float4 o = make_float4(fmaxf(h0+be0,0.f), fmaxf(h1+be1,0.f),
                                   fmaxf(h2+be2,0.f), fmaxf(h3+be3,0.f));
            *(float4*)(hout + (size_t)(r+1) * HIDN + c0) = o;
        }
    }
}

// ---------------- K2: per-row top-20 gating (in place on h) ----------------
// Warp per row. Values are post-ReLU (>= 0) so float ordering == uint-bit
// ordering. 64-bit key = (value_bits << 32) | (inverted index) for exact
// tie-breaking matching top_k's lower-index preference. Extract max 20 times;
// mask = (v >= 20th value). If threshold == 0 (fewer than 20 positives),
// keeping every v >= 0 is exactly equivalent (selected zeros contribute 0).
__global__ __launch_bounds__(256) void k_topk(float* __restrict__ h, int B) {
    int warp = threadIdx.x >> 5, lane = threadIdx.x & 31;
    int row = blockIdx.x * 8 + warp;
    if (row >= B) return;
    float* hr = h + (size_t)row * HIDN;
    float v0 = hr[lane], v1 = hr[lane + 32];
    unsigned long long k0 = ((unsigned long long)__float_as_uint(v0) << 32) | (unsigned)(63 - lane);
    unsigned long long k1 = ((unsigned long long)__float_as_uint(v1) << 32) | (unsigned)(31 - lane);
    float thr = 0.f;
    #pragma unroll
    for (int it = 0; it < KTOP; it++) {
        unsigned long long m = (k0 > k1) ? k0 : k1;
        #pragma unroll
        for (int off = 16; off > 0; off >>= 1) {
            unsigned long long o = __shfl_xor_sync(0xffffffffu, m, off);
            if (o > m) m = o;
        }
        if (it == KTOP - 1) thr = __uint_as_float((unsigned)(m >> 32));
        if (k0 == m) k0 = 0ull; else if (k1 == m) k1 = 0ull;
    }
    hr[lane]      = (v0 >= thr) ? v0 : 0.f;
    hr[lane + 32] = (v1 >= thr) ? v1 : 0.f;
}

// ---------------- K3: decoder GEMM (dense, K=64) + bias ----------------
// CTA: 96 rows x 64 cols. Thread tile 6 rows x 4 cols; accumulators packed
// as column-pairs (b-operand pairs come straight out of smem, a duplicated).
__global__ __launch_bounds__(256) void k_dec(const float* __restrict__ h,
        const float* __restrict__ bdec, float* __restrict__ xhat, int B) {
    __shared__ float hs[96][64];    // h tile, natural layout
    __shared__ float ws[64][64];    // WtD[k][n0..n0+63]
    const int tid = threadIdx.x;
    const int tx = tid & 15, ty = tid >> 4;
    const int r0 = blockIdx.x * 96;
    const int n0 = blockIdx.y * 64;
    const int c0 = tx * 4;

    #pragma unroll
    for (int i = 0; i < 6; i++) {
        int fidx = tid + i * 256;          // 0..1535
        int row = fidx >> 4, j4 = fidx & 15;
        int gr = r0 + row; if (gr >= B) gr = B - 1;
        *(float4*)&hs[row][j4*4] = *(const float4*)(h + (size_t)gr * HIDN + j4 * 4);
    }
    #pragma unroll
    for (int i = 0; i < 4; i++) {
        int fidx = tid + i * 256;          // 0..1023
        int k = fidx >> 4, j4 = fidx & 15;
        int col = n0 + j4 * 4;
        float4 w = make_float4(0.f, 0.f, 0.f, 0.f);
        if (col < IN) w = *(const float4*)(g_WtD + (size_t)k * IN + col);
        *(float4*)&ws[k][j4*4] = w;
    }
    __syncthreads();

    unsigned long long acc[6][2];
    #pragma unroll
    for (int r = 0; r < 6; r++) { acc[r][0] = 0ull; acc[r][1] = 0ull; }

    #pragma unroll 8
    for (int k = 0; k < 64; k++) {
        ulonglong2 b2 = *(const ulonglong2*)&ws[k][c0];   // cols (c0,c0+1),(c0+2,c0+3)
        #pragma unroll
        for (int r = 0; r < 6; r++) {
            unsigned long long ad = pk_dup(hs[ty * 6 + r][k]);
            fma2(acc[r][0], ad, b2.x);
            fma2(acc[r][1], ad, b2.y);
        }
    }

    int col = n0 + c0;
    if (col < IN) {
        float be0 = bdec[col], be1 = bdec[col+1], be2 = bdec[col+2], be3 = bdec[col+3];
        #pragma unroll
        for (int r = 0; r < 6; r++) {
            int gr = r0 + ty * 6 + r;
            if (gr < B) {
                float o0, o1, o2, o3;
                upk(acc[r][0], o0, o1); upk(acc[r][1], o2, o3);
                float4 o = make_float4(o0 + be0, o1 + be1, o2 + be2, o3 + be3);
                *(float4*)(xhat + (size_t)gr * IN + col) = o;
            }
        }
    }
}

extern "C" void kernel_launch(void* const* d_in, const int* in_sizes, int n_in,
                              void* d_out, int out_size) {
    const float* x    = (const float*)d_in[0];
    const float* We   = (const float*)d_in[1];
    const float* benc = (const float*)d_in[2];
    const float* Wd   = (const float*)d_in[3];
    const float* bdec = (const float*)d_in[4];
    int B = in_sizes[0] / IN;

    float* hout = (float*)d_out;                         // [B, 64]
    float* xhat = (float*)d_out + (size_t)B * HIDN;      // [B, 784]

    k_prep<<<(IN * HIDN + 255) / 256, 256>>>(We, Wd);
    k_enc<<<(B + 127) / 128, 256>>>(x, benc, hout, B);
    k_topk<<<(B + 7) / 8, 256>>>(hout, B);
    k_dec<<<dim3((B + 95) / 96, (IN + 63) / 64), 256>>>(hout, bdec, xhat, B);
}